// round 1
// baseline (speedup 1.0000x reference)
#include <cuda_runtime.h>

#define L_DIM 8192
#define B_DIM 4096
#define RANK 8
#define M_SPLITS 32
#define M_CHUNK (L_DIM / M_SPLITS)   // 256
#define B4 (B_DIM / 4)               // 1024 float4 lanes
#define L_TILE 32

// scratch for T = V @ inputs  -> [RANK, B]
__device__ float g_T[RANK * B_DIM];

__global__ void zero_T_kernel() {
    int i = blockIdx.x * blockDim.x + threadIdx.x;
    if (i < RANK * B_DIM) g_T[i] = 0.0f;
}

// T[r, b] += sum_{m in chunk} V[r, m] * inputs[m, b]
// grid: (B4/256 = 4, M_SPLITS = 32), block: 256
__global__ void vx_kernel(const float* __restrict__ inp,
                          const float* __restrict__ V) {
    __shared__ float Vs[RANK][M_CHUNK];   // 8 KB

    const int m0 = blockIdx.y * M_CHUNK;
    for (int i = threadIdx.x; i < RANK * M_CHUNK; i += blockDim.x) {
        int r = i / M_CHUNK;
        int mi = i - r * M_CHUNK;
        Vs[r][mi] = V[r * L_DIM + m0 + mi];
    }
    __syncthreads();

    const int b4 = blockIdx.x * blockDim.x + threadIdx.x;  // 0..1023
    const float4* in4 = (const float4*)inp;

    float4 acc[RANK];
    #pragma unroll
    for (int r = 0; r < RANK; r++) acc[r] = make_float4(0.f, 0.f, 0.f, 0.f);

    #pragma unroll 4
    for (int mi = 0; mi < M_CHUNK; mi++) {
        float4 x = in4[(size_t)(m0 + mi) * B4 + b4];
        #pragma unroll
        for (int r = 0; r < RANK; r++) {
            float v = Vs[r][mi];
            acc[r].x = fmaf(v, x.x, acc[r].x);
            acc[r].y = fmaf(v, x.y, acc[r].y);
            acc[r].z = fmaf(v, x.z, acc[r].z);
            acc[r].w = fmaf(v, x.w, acc[r].w);
        }
    }

    const int b = b4 * 4;
    #pragma unroll
    for (int r = 0; r < RANK; r++) {
        atomicAdd(&g_T[r * B_DIM + b + 0], acc[r].x);
        atomicAdd(&g_T[r * B_DIM + b + 1], acc[r].y);
        atomicAdd(&g_T[r * B_DIM + b + 2], acc[r].z);
        atomicAdd(&g_T[r * B_DIM + b + 3], acc[r].w);
    }
}

// out[l, b] = sum_r U[r, l] * T[r, b]
// grid: (B4/256 = 4, L_DIM / L_TILE = 256), block: 256
__global__ void out_kernel(const float* __restrict__ U,
                           float* __restrict__ out) {
    __shared__ float Us[RANK][L_TILE];    // 1 KB

    const int l0 = blockIdx.y * L_TILE;
    for (int i = threadIdx.x; i < RANK * L_TILE; i += blockDim.x) {
        int r = i / L_TILE;
        int li = i - r * L_TILE;
        Us[r][li] = U[r * L_DIM + l0 + li];
    }
    __syncthreads();

    const int b4 = blockIdx.x * blockDim.x + threadIdx.x;  // 0..1023
    const float4* T4 = (const float4*)g_T;

    float4 t[RANK];
    #pragma unroll
    for (int r = 0; r < RANK; r++) t[r] = T4[r * B4 + b4];

    float4* out4 = (float4*)out;
    #pragma unroll 4
    for (int li = 0; li < L_TILE; li++) {
        float4 acc = make_float4(0.f, 0.f, 0.f, 0.f);
        #pragma unroll
        for (int r = 0; r < RANK; r++) {
            float u = Us[r][li];
            acc.x = fmaf(u, t[r].x, acc.x);
            acc.y = fmaf(u, t[r].y, acc.y);
            acc.z = fmaf(u, t[r].z, acc.z);
            acc.w = fmaf(u, t[r].w, acc.w);
        }
        out4[(size_t)(l0 + li) * B4 + b4] = acc;
    }
}

extern "C" void kernel_launch(void* const* d_in, const int* in_sizes, int n_in,
                              void* d_out, int out_size) {
    const float* inp = (const float*)d_in[0];  // [L, B]
    const float* U   = (const float*)d_in[1];  // [RANK, L]
    const float* V   = (const float*)d_in[2];  // [RANK, L]
    float* out = (float*)d_out;                // [L, B]

    zero_T_kernel<<<(RANK * B_DIM + 255) / 256, 256>>>();

    dim3 g1(B4 / 256, M_SPLITS);
    vx_kernel<<<g1, 256>>>(inp, V);

    dim3 g2(B4 / 256, L_DIM / L_TILE);
    out_kernel<<<g2, 256>>>(U, out);
}

// round 2
// speedup vs baseline: 1.5360x; 1.5360x over previous
#include <cuda_runtime.h>

#define L_DIM 8192
#define B_DIM 4096
#define RANK 8
#define M_SPLITS 128
#define M_CHUNK (L_DIM / M_SPLITS)   // 64
#define B4 (B_DIM / 4)               // 1024 float4 lanes
#define L_TILE 32

// per-split partials: [M_SPLITS][RANK][B_DIM] = 16 MB
__device__ float g_part[M_SPLITS * RANK * B_DIM];
// reduced T = V @ inputs -> [RANK, B]
__device__ float g_T[RANK * B_DIM];

// stage 1: part[s, r, b] = sum_{m in chunk s} V[r, m] * inputs[m, b]
// grid: (B4/256 = 4, M_SPLITS = 128), block: 256
__global__ __launch_bounds__(256) void vx_part_kernel(
    const float* __restrict__ inp, const float* __restrict__ V) {
    __shared__ float Vs[RANK][M_CHUNK];   // 2 KB

    const int s = blockIdx.y;
    const int m0 = s * M_CHUNK;
    for (int i = threadIdx.x; i < RANK * M_CHUNK; i += blockDim.x) {
        int r = i / M_CHUNK;
        int mi = i - r * M_CHUNK;
        Vs[r][mi] = V[r * L_DIM + m0 + mi];
    }
    __syncthreads();

    const int b4 = blockIdx.x * blockDim.x + threadIdx.x;  // 0..1023
    const float4* in4 = (const float4*)inp;

    float4 acc[RANK];
    #pragma unroll
    for (int r = 0; r < RANK; r++) acc[r] = make_float4(0.f, 0.f, 0.f, 0.f);

    #pragma unroll 8
    for (int mi = 0; mi < M_CHUNK; mi++) {
        float4 x = in4[(size_t)(m0 + mi) * B4 + b4];
        #pragma unroll
        for (int r = 0; r < RANK; r++) {
            float v = Vs[r][mi];
            acc[r].x = fmaf(v, x.x, acc[r].x);
            acc[r].y = fmaf(v, x.y, acc[r].y);
            acc[r].z = fmaf(v, x.z, acc[r].z);
            acc[r].w = fmaf(v, x.w, acc[r].w);
        }
    }

    float4* p4 = (float4*)g_part;
    #pragma unroll
    for (int r = 0; r < RANK; r++) {
        p4[((size_t)s * RANK + r) * B4 + b4] = acc[r];
    }
}

// stage 2: T[r, b] = sum_s part[s, r, b]
// grid: RANK*B4/256 = 32 blocks, block: 256 (one float4 per thread)
__global__ __launch_bounds__(256) void reduce_kernel() {
    const int idx = blockIdx.x * blockDim.x + threadIdx.x;  // 0..8191 (RANK*B4)
    const float4* p4 = (const float4*)g_part;

    float4 acc = make_float4(0.f, 0.f, 0.f, 0.f);
    #pragma unroll 8
    for (int s = 0; s < M_SPLITS; s++) {
        float4 x = p4[(size_t)s * RANK * B4 + idx];
        acc.x += x.x; acc.y += x.y; acc.z += x.z; acc.w += x.w;
    }
    ((float4*)g_T)[idx] = acc;
}

// stage 3: out[l, b] = sum_r U[r, l] * T[r, b]
// grid: (B4/256 = 4, L_DIM / L_TILE = 256), block: 256
__global__ __launch_bounds__(256) void out_kernel(
    const float* __restrict__ U, float* __restrict__ out) {
    __shared__ float Us[RANK][L_TILE];    // 1 KB

    const int l0 = blockIdx.y * L_TILE;
    for (int i = threadIdx.x; i < RANK * L_TILE; i += blockDim.x) {
        int r = i / L_TILE;
        int li = i - r * L_TILE;
        Us[r][li] = U[r * L_DIM + l0 + li];
    }
    __syncthreads();

    const int b4 = blockIdx.x * blockDim.x + threadIdx.x;  // 0..1023
    const float4* T4 = (const float4*)g_T;

    float4 t[RANK];
    #pragma unroll
    for (int r = 0; r < RANK; r++) t[r] = T4[r * B4 + b4];

    float4* out4 = (float4*)out;
    #pragma unroll 4
    for (int li = 0; li < L_TILE; li++) {
        float4 acc = make_float4(0.f, 0.f, 0.f, 0.f);
        #pragma unroll
        for (int r = 0; r < RANK; r++) {
            float u = Us[r][li];
            acc.x = fmaf(u, t[r].x, acc.x);
            acc.y = fmaf(u, t[r].y, acc.y);
            acc.z = fmaf(u, t[r].z, acc.z);
            acc.w = fmaf(u, t[r].w, acc.w);
        }
        out4[(size_t)(l0 + li) * B4 + b4] = acc;
    }
}

extern "C" void kernel_launch(void* const* d_in, const int* in_sizes, int n_in,
                              void* d_out, int out_size) {
    const float* inp = (const float*)d_in[0];  // [L, B]
    const float* U   = (const float*)d_in[1];  // [RANK, L]
    const float* V   = (const float*)d_in[2];  // [RANK, L]
    float* out = (float*)d_out;                // [L, B]

    dim3 g1(B4 / 256, M_SPLITS);
    vx_part_kernel<<<g1, 256>>>(inp, V);

    reduce_kernel<<<(RANK * B4) / 256, 256>>>();

    dim3 g3(B4 / 256, L_DIM / L_TILE);
    out_kernel<<<g3, 256>>>(U, out);
}